// round 5
// baseline (speedup 1.0000x reference)
#include <cuda_runtime.h>
#include <cstdint>

// Kuramoto oscillators: B=32, N=2048, K=8, T=20.
// R5: cluster of 4 CTAs per batch (grid=128). Replicated double-buffered
// phase arrays. Fine-grained producer-push comms: each thread, right after
// computing its new phase, issues 4x st.async (one per cluster CTA, incl.
// itself) with mbarrier::complete_tx byte counting into that CTA's per-buffer
// mbarrier (expect = 4*512*4 = 8192 B). No in-loop __syncthreads, no fence,
// no bulk engine: stores stream out while other warps still compute.
// Consumers wait with try_wait.parity.acquire.cluster (~60-90 cyc wakeup).
// Duplicate scatter targets: LAST k wins; n = #distinct nonzero targets.
// eps/n folded into the weights (eps=1, anneal=0).

#define Nn 2048
#define Kk 8
#define Bb 32
#define Tt 20
#define CSZ 4
#define THREADS 512
#define NPC (Nn / CSZ)                       // 512 oscillators per CTA
#define EXPECT_BYTES (CSZ * THREADS * 4)     // 8192 bytes per buffer per step

#define TWO_PI     6.28318530717958647692f
#define INV_TWO_PI 0.15915494309189533577f

__device__ __forceinline__ uint32_t smem_u32(const void* p) {
    uint32_t a;
    asm("{ .reg .u64 t; cvta.to.shared.u64 t, %1; cvt.u32.u64 %0, t; }"
        : "=r"(a) : "l"(p));
    return a;
}

__device__ __forceinline__ uint32_t mapa_u32(uint32_t laddr, uint32_t rank) {
    uint32_t r;
    asm("mapa.shared::cluster.u32 %0, %1, %2;" : "=r"(r) : "r"(laddr), "r"(rank));
    return r;
}

__device__ __forceinline__ void mbar_init(uint32_t laddr, uint32_t count) {
    asm volatile("mbarrier.init.shared.b64 [%0], %1;" :: "r"(laddr), "r"(count) : "memory");
}

__device__ __forceinline__ void mbar_arrive_expect_tx(uint32_t laddr, uint32_t tx) {
    asm volatile("mbarrier.arrive.expect_tx.shared.b64 _, [%0], %1;"
                 :: "r"(laddr), "r"(tx) : "memory");
}

// store 4 bytes into a (possibly remote) cluster CTA's smem, counting the
// bytes on that CTA's mbarrier.
__device__ __forceinline__ void st_async_b32(uint32_t raddr, uint32_t v,
                                             uint32_t rmbar) {
    asm volatile(
        "st.async.shared::cluster.mbarrier::complete_tx::bytes.b32 [%0], %1, [%2];"
        :: "r"(raddr), "r"(v), "r"(rmbar) : "memory");
}

__device__ __forceinline__ void mbar_wait(uint32_t laddr, uint32_t parity) {
    uint32_t done;
    asm volatile(
        "{ .reg .pred p;\n"
        "  mbarrier.try_wait.parity.acquire.cluster.shared::cta.b64 p, [%1], %2;\n"
        "  selp.b32 %0, 1, 0, p; }"
        : "=r"(done) : "r"(laddr), "r"(parity) : "memory");
    if (!done) {
        asm volatile(
            "{ .reg .pred p;\n"
            "WL_%=:\n"
            "  mbarrier.try_wait.parity.acquire.cluster.shared::cta.b64 p, [%0], %1, 0x989680;\n"
            "  @p bra.uni WD_%=;\n"
            "  bra.uni WL_%=;\n"
            "WD_%=: }"
            :: "r"(laddr), "r"(parity) : "memory");
    }
}

__global__ void __launch_bounds__(THREADS, 1) __cluster_dims__(CSZ, 1, 1)
osc_kernel(const float* __restrict__ coupling,   // [B,N,K]
           const float* __restrict__ phase0,     // [B,N]
           const float* __restrict__ omega,      // [B,N]
           const int*   __restrict__ conn,       // [N,K]
           float*       __restrict__ out)        // [T+1,B,N]
{
    __shared__ __align__(16) float th[2][Nn];             // replicated phases
    __shared__ __align__(8)  unsigned long long mbar[2];  // one per buffer

    uint32_t rank;
    asm("mov.u32 %0, %%cluster_ctarank;" : "=r"(rank));
    const int b   = blockIdx.x / CSZ;
    const int tid = threadIdx.x;
    const int n   = (int)rank * NPC + tid;

    const uint32_t mb_l0 = smem_u32(&mbar[0]);
    const uint32_t mb_l1 = smem_u32(&mbar[1]);
    if (tid == 0) {
        mbar_init(mb_l0, 1);   // 1 arrival (thread0 arming) + tx bytes
        mbar_init(mb_l1, 1);
    }

    // ---- prologue: dedup couplings, fold eps/n into weights ----
    float w[Kk];
    int   off[Kk];
    int idx[Kk];
    #pragma unroll
    for (int k = 0; k < Kk; ++k) idx[k] = conn[n * Kk + k];

    int cnt = 0;
    #pragma unroll
    for (int k = 0; k < Kk; ++k) {
        bool win = true;
        #pragma unroll
        for (int k2 = k + 1; k2 < Kk; ++k2) win = win && (idx[k2] != idx[k]);
        const float c = coupling[((size_t)b * Nn + n) * Kk + k];
        w[k]   = win ? c : 0.0f;
        off[k] = idx[k];
        cnt += (win && (c != 0.0f)) ? 1 : 0;
    }
    const float inv = (cnt > 0) ? (1.0f / (float)cnt) : 0.0f;
    #pragma unroll
    for (int k = 0; k < Kk; ++k) w[k] *= inv;

    float p  = phase0[(size_t)b * Nn + n];
    const float om = omega[(size_t)b * Nn + n];
    out[(size_t)b * Nn + n] = p;                 // t=0 slice

    // each CTA fills its FULL th[0] locally from gmem
    #pragma unroll
    for (int j = 0; j < CSZ; ++j) {
        const int m  = tid + j * THREADS;
        const float q = phase0[(size_t)b * Nn + m];
        th[0][m] = q - TWO_PI * rintf(q * INV_TWO_PI);
    }
    float pr = p - TWO_PI * rintf(p * INV_TWO_PI);

    // hoisted per-thread destination + barrier addresses (2 buffers x 4 CTAs)
    uint32_t dst[2][CSZ], mbr[2][CSZ];
    {
        const uint32_t a0 = smem_u32(&th[0][n]);
        const uint32_t a1 = smem_u32(&th[1][n]);
        #pragma unroll
        for (int r = 0; r < CSZ; ++r) {
            dst[0][r] = mapa_u32(a0, (uint32_t)r);
            dst[1][r] = mapa_u32(a1, (uint32_t)r);
            mbr[0][r] = mapa_u32(mb_l0, (uint32_t)r);
            mbr[1][r] = mapa_u32(mb_l1, (uint32_t)r);
        }
    }

    __syncthreads();   // th[0] + mbarrier init complete at CTA scope
    // cluster-wide: all mbarriers initialized before any peer st.async signals
    asm volatile("barrier.cluster.arrive.aligned;" ::: "memory");
    asm volatile("barrier.cluster.wait.aligned;"   ::: "memory");

    uint32_t par[2] = {0, 0};

    // ---- time stepping ----
    #pragma unroll 1
    for (int t = 0; t < Tt; ++t) {
        const int c  = t & 1;
        const int nb = c ^ 1;
        const uint32_t mb_cur = c ? mb_l1 : mb_l0;
        const uint32_t mb_nxt = c ? mb_l0 : mb_l1;

        if (t > 0) {                // all 8192 bytes of buffer c arrived
            mbar_wait(mb_cur, par[c]);
            par[c] ^= 1u;
        }
        if (t < Tt - 1 && tid == 0) {
            mbar_arrive_expect_tx(mb_nxt, EXPECT_BYTES);
        }

        const float* __restrict__ cur = th[c];

        float acc = 0.0f;
        #pragma unroll
        for (int k = 0; k < Kk; ++k)
            acc += w[k] * __sinf(cur[off[k]] - pr);   // arg in [-2pi, 2pi]

        p += acc + om;
        const float prn = p - TWO_PI * rintf(p * INV_TWO_PI);
        pr = prn;

        // global output (independent, overlaps the sends)
        out[(size_t)(t + 1) * (Bb * Nn) + (size_t)b * Nn + n] = p;

        if (t < Tt - 1) {
            const uint32_t bits = __float_as_uint(prn);
            #pragma unroll
            for (int r = 0; r < CSZ; ++r)
                st_async_b32(dst[nb][r], bits, mbr[nb][r]);
        }
    }
}

extern "C" void kernel_launch(void* const* d_in, const int* in_sizes, int n_in,
                              void* d_out, int out_size)
{
    const float* coupling = (const float*)d_in[0];   // [B,N,K] f32
    const float* phase0   = (const float*)d_in[1];   // [B,N]   f32
    const float* omega    = (const float*)d_in[2];   // [B,N]   f32
    const int*   conn     = (const int*)  d_in[3];   // [N,K]   i32
    float*       out      = (float*)d_out;           // [T+1,B,N] f32

    osc_kernel<<<Bb * CSZ, THREADS>>>(coupling, phase0, omega, conn, out);
}